// round 16
// baseline (speedup 1.0000x reference)
#include <cuda_runtime.h>
#include <cuda_bf16.h>
#include <math.h>
#include <stdint.h>

// Problem constants
#define CB 8
#define CS 1024
#define CF 1024
#define CFFN 4096
#define CNC 2048
#define CR 64
#define CBS (CB*CS)          // 8192
#define NSTEPS 6
#define NMF_EPS 1e-6f
#define CLN_EPS 1e-5f
#define GSPLIT 8             // K-split for Gram matrices
#define NSPL 2               // K-split for numn tensor GEMM
#define DSPL 4               // K-split for numd tensor GEMM

// tensor GEMM config
#define NST 3                // cp.async pipeline stages
#define KC 64                // bf16 K elements per chunk (128B rows, SW128)
#define TCSMEM (NST * 32768)
#define TC64SMEM (NST * 24576)

// ------------------------------------------------------------------
// Device scratch (allocation-free rule: __device__ globals)
// ------------------------------------------------------------------
__device__ float g_z1[(size_t)CBS * CNC];            // 64 MB
__device__ float g_xm[(size_t)CBS * CNC];            // 64 MB (z2 pre-LN only)
__device__ float g_coef [CB * CNC * CR];
__device__ float g_bases[CB * CS  * CR];
__device__ float g_numn [NSPL * CB * CNC * CR];      // 8 MB (2 K-partials)
__device__ float g_numd [DSPL * CB * CS  * CR];      // 8 MB (4 K-partials)
__device__ float g_btb  [GSPLIT * CB * CR * CR];
__device__ float g_ctc  [GSPLIT * CB * CR * CR];
// split-bf16 packed operands: [rows][2K] = (hi | lo)
__device__ __nv_bfloat16 g_xh2  [(size_t)CBS * 2 * CF];    // 32 MB
__device__ __nv_bfloat16 g_uw2  [(size_t)CFFN * 2 * CF];   // 16 MB
__device__ __nv_bfloat16 g_gate2[(size_t)CBS * 2 * CNC];   // 64 MB (xmD2, then gated)
__device__ __nv_bfloat16 g_vw2  [(size_t)CF * 2 * CNC];    // 8 MB
// NMF tensor-core operands
__device__ __nv_bfloat16 g_xmT2 [(size_t)CB * CNC * 2 * CS];  // 64 MB: xm^T hi|lo [n][2D]
__device__ __nv_bfloat16 g_basT2[(size_t)CB * CR * 2 * CS];   // 2 MB
__device__ __nv_bfloat16 g_cofT2[(size_t)CB * CR * 2 * CNC];  // 4 MB

#define PARTN ((long)CB * CNC * CR)
#define PARTD ((long)CB * CS * CR)

__device__ __forceinline__ float gelu_exact(float v) {
    return 0.5f * v * (1.0f + erff(v * 0.70710678118654752440f));
}

// ------------------------------------------------------------------
// PTX helpers (all baseline sm_80+ instructions; no tcgen05)
// ------------------------------------------------------------------
__device__ __forceinline__ uint32_t smem_u32(const void* p) {
    uint32_t a;
    asm("{ .reg .u64 t; cvta.to.shared.u64 t, %1; cvt.u32.u64 %0, t; }" : "=r"(a) : "l"(p));
    return a;
}
__device__ __forceinline__ void cp16(uint32_t dst, const void* src) {
    asm volatile("cp.async.cg.shared.global [%0], [%1], 16;" :: "r"(dst), "l"(src));
}
__device__ __forceinline__ void ldm4(uint32_t* r, uint32_t addr) {
    asm volatile("ldmatrix.sync.aligned.m8n8.x4.shared.b16 {%0,%1,%2,%3}, [%4];"
                 : "=r"(r[0]), "=r"(r[1]), "=r"(r[2]), "=r"(r[3]) : "r"(addr));
}
__device__ __forceinline__ void mma16816(float* d, const uint32_t* a, uint32_t b0, uint32_t b1) {
    asm volatile("mma.sync.aligned.m16n8k16.row.col.f32.bf16.bf16.f32 "
                 "{%0,%1,%2,%3}, {%4,%5,%6,%7}, {%8,%9}, {%0,%1,%2,%3};"
                 : "+f"(d[0]), "+f"(d[1]), "+f"(d[2]), "+f"(d[3])
                 : "r"(a[0]), "r"(a[1]), "r"(a[2]), "r"(a[3]), "r"(b0), "r"(b1));
}

// ------------------------------------------------------------------
// Split pack: fp32 [rows][K] -> bf16 [rows][2K] = hi | lo.  K = 1<<kb.
// ------------------------------------------------------------------
__device__ __forceinline__ uint32_t bpair(float a, float b) {
    __nv_bfloat162 t = __floats2bfloat162_rn(a, b);
    return *reinterpret_cast<uint32_t*>(&t);
}
__global__ void __launch_bounds__(256) pack_kernel(
    const float* __restrict__ in, __nv_bfloat16* __restrict__ out, int kb, int total4)
{
    const int i = blockIdx.x * 256 + threadIdx.x;
    if (i >= total4) return;
    const int base = i << 2;
    const int K = 1 << kb;
    const int m = base >> kb;
    const int k = base & (K - 1);
    const float4 v = *(const float4*)(in + (size_t)base);
    const float h0 = __bfloat162float(__float2bfloat16(v.x));
    const float h1 = __bfloat162float(__float2bfloat16(v.y));
    const float h2 = __bfloat162float(__float2bfloat16(v.z));
    const float h3 = __bfloat162float(__float2bfloat16(v.w));
    uint2 hv, lv;
    hv.x = bpair(v.x, v.y);           hv.y = bpair(v.z, v.w);
    lv.x = bpair(v.x - h0, v.y - h1); lv.y = bpair(v.z - h2, v.w - h3);
    __nv_bfloat16* o = out + ((size_t)m << (kb + 1)) + k;
    *(uint2*)o       = hv;
    *(uint2*)(o + K) = lv;
}

// ------------------------------------------------------------------
// Transpose + split pack, fp32 source: [D][N] -> [N][2D] hi|lo
// ------------------------------------------------------------------
__global__ void __launch_bounds__(256) transpack_kernel(
    const float* __restrict__ src, __nv_bfloat16* __restrict__ dst,
    int D, int N, long sStride, long dStride)
{
    __shared__ float t[32][33];
    const float* s = src + (long)blockIdx.z * sStride;
    __nv_bfloat16* d = dst + (long)blockIdx.z * dStride;
    const int n0 = blockIdx.x * 32, d0 = blockIdx.y * 32;
#pragma unroll
    for (int j = threadIdx.y; j < 32; j += 8)
        t[j][threadIdx.x] = s[(size_t)(d0 + j) * N + n0 + threadIdx.x];
    __syncthreads();
#pragma unroll
    for (int j = threadIdx.y; j < 32; j += 8) {
        const int n = n0 + j;
        const int dd = d0 + threadIdx.x;
        const float v = t[threadIdx.x][j];
        const __nv_bfloat16 h = __float2bfloat16(v);
        __nv_bfloat16* row = d + (size_t)n * 2 * D;
        row[dd]     = h;
        row[D + dd] = __float2bfloat16(v - __bfloat162float(h));
    }
}

// ------------------------------------------------------------------
// Transpose + split pack, bf16-pair source: src [D][2N] hi|lo -> dst [N][2D] hi|lo
// ------------------------------------------------------------------
__global__ void __launch_bounds__(256) transpack_bf_kernel(
    const __nv_bfloat16* __restrict__ src, __nv_bfloat16* __restrict__ dst,
    int D, int N, long sStride, long dStride)
{
    __shared__ float t[32][33];
    const __nv_bfloat16* s = src + (long)blockIdx.z * sStride;
    __nv_bfloat16* d = dst + (long)blockIdx.z * dStride;
    const int n0 = blockIdx.x * 32, d0 = blockIdx.y * 32;
#pragma unroll
    for (int j = threadIdx.y; j < 32; j += 8) {
        const size_t row = (size_t)(d0 + j) * 2 * N;
        t[j][threadIdx.x] = __bfloat162float(s[row + n0 + threadIdx.x])
                          + __bfloat162float(s[row + N + n0 + threadIdx.x]);
    }
    __syncthreads();
#pragma unroll
    for (int j = threadIdx.y; j < 32; j += 8) {
        const int n = n0 + j;
        const int dd = d0 + threadIdx.x;
        const float v = t[threadIdx.x][j];
        const __nv_bfloat16 h = __float2bfloat16(v);
        __nv_bfloat16* row = d + (size_t)n * 2 * D;
        row[dd]     = h;
        row[D + dd] = __float2bfloat16(v - __bfloat162float(h));
    }
}

// ------------------------------------------------------------------
// Tensor-core split-bf16 NT GEMM: C[M,N] = A[M,K] * B[N,K]^T + bias
// (fp32 via 3 bf16 passes). 128x128 CTA tile, 8 warps, BK=64, 3-stage ring.
// MODE 0: gelu epilogue, split store z1/xm.  MODE 1: bias store to C0.
// ------------------------------------------------------------------
template <int MODE>
__global__ void __launch_bounds__(256, 2)
gemm_tc_kernel(const __nv_bfloat16* __restrict__ A2, const __nv_bfloat16* __restrict__ B2,
               const float* __restrict__ bias, float* __restrict__ C0, float* __restrict__ C1,
               int Kf, int Nfull)
{
    extern __shared__ char smem[];
    const uint32_t sbase = smem_u32(smem);
    const int tid = threadIdx.x;
    const int wid = tid >> 5, L = tid & 31;
    const int bm = blockIdx.y * 128, bn = blockIdx.x * 128;
    const int warp_m = wid & 3, warp_n = wid >> 2;
    const size_t ld2 = 2 * (size_t)Kf;
    const int CPP = Kf / KC;
    const int NCH = 3 * CPP;

    const int lrow = tid >> 3;
    const int lc16 = tid & 7;
    const int scol = (lc16 * 16) ^ ((lrow & 7) << 4);

    auto issue = [&](int c) {
        const int s = c % NST;
        const int p = c / CPP;
        const int kc = (c - p * CPP) * KC;
        const int aoff = (p == 2) ? Kf : 0;
        const int boff = (p == 1) ? Kf : 0;
        const __nv_bfloat16* Ap = A2 + (size_t)bm * ld2 + aoff + kc + lc16 * 8;
        const __nv_bfloat16* Bp = B2 + (size_t)bn * ld2 + boff + kc + lc16 * 8;
        const uint32_t stA = sbase + s * 32768;
        const uint32_t stB = stA + 16384;
#pragma unroll
        for (int j = 0; j < 4; j++) {
            const int r = lrow + j * 32;
            cp16(stA + r * 128 + scol, Ap + (size_t)r * ld2);
            cp16(stB + r * 128 + scol, Bp + (size_t)r * ld2);
        }
        asm volatile("cp.async.commit_group;" ::: "memory");
    };

    float acc[2][8][4];
#pragma unroll
    for (int i = 0; i < 2; i++)
#pragma unroll
        for (int j = 0; j < 8; j++)
#pragma unroll
            for (int k = 0; k < 4; k++) acc[i][j][k] = 0.f;

    issue(0);
    issue(1);

    const int lrow16 = L & 15;
    const int lhi = (L >> 4) * 16;
    const int lxor = (L & 7) << 4;
    const uint32_t a_row = (uint32_t)(warp_m * 32 + lrow16) * 128;
    const uint32_t b_row = (uint32_t)(warp_n * 64 + lrow16) * 128;

    for (int c = 0; c < NCH; c++) {
        if (c + 1 < NCH) asm volatile("cp.async.wait_group 1;" ::: "memory");
        else             asm volatile("cp.async.wait_group 0;" ::: "memory");
        __syncthreads();
        if (c + 2 < NCH) issue(c + 2);
        const int s = c % NST;
        const uint32_t stA = sbase + s * 32768;
        const uint32_t stB = stA + 16384;
#pragma unroll
        for (int ks = 0; ks < 4; ks++) {
            uint32_t af[2][4], bf[4][4];
            const uint32_t coff = (uint32_t)((ks * 32 + lhi) ^ lxor);
#pragma unroll
            for (int mf = 0; mf < 2; mf++)
                ldm4(af[mf], stA + a_row + mf * 2048 + coff);
#pragma unroll
            for (int nf = 0; nf < 4; nf++)
                ldm4(bf[nf], stB + b_row + nf * 2048 + coff);
#pragma unroll
            for (int mf = 0; mf < 2; mf++)
#pragma unroll
                for (int ng = 0; ng < 8; ng++)
                    mma16816(acc[mf][ng], af[mf],
                             bf[ng >> 1][ng & 1], bf[ng >> 1][(ng & 1) + 2]);
        }
    }
    __syncthreads();

    const int q = L >> 2, t2 = (L & 3) * 2;
#pragma unroll
    for (int mf = 0; mf < 2; mf++) {
        const int r0 = bm + warp_m * 32 + mf * 16 + q;
        const int r1 = r0 + 8;
#pragma unroll
        for (int ng = 0; ng < 8; ng++) {
            const int col = bn + warp_n * 64 + ng * 8 + t2;
            const float b0v = __ldg(bias + col), b1v = __ldg(bias + col + 1);
            float v00 = acc[mf][ng][0] + b0v, v01 = acc[mf][ng][1] + b1v;
            float v10 = acc[mf][ng][2] + b0v, v11 = acc[mf][ng][3] + b1v;
            if (MODE == 0) {
                v00 = gelu_exact(v00); v01 = gelu_exact(v01);
                v10 = gelu_exact(v10); v11 = gelu_exact(v11);
                if (col < CNC) {
                    *(float2*)(C0 + (size_t)r0 * CNC + col) = make_float2(v00, v01);
                    *(float2*)(C0 + (size_t)r1 * CNC + col) = make_float2(v10, v11);
                } else {
                    *(float2*)(C1 + (size_t)r0 * CNC + (col - CNC)) = make_float2(v00, v01);
                    *(float2*)(C1 + (size_t)r1 * CNC + (col - CNC)) = make_float2(v10, v11);
                }
            } else {
                *(float2*)(C0 + (size_t)r0 * Nfull + col) = make_float2(v00, v01);
                *(float2*)(C0 + (size_t)r1 * Nfull + col) = make_float2(v10, v11);
            }
        }
    }
}

// ------------------------------------------------------------------
// Skinny tensor-core split-bf16 NT GEMM with K-split:
// C_part[y][M,64] = A[M, koff:koff+Kloc] * B[64, koff:koff+Kloc]^T
// grid (M/128, ksplit, B); partial y written at Cg + z*sC + y*pC.
// ------------------------------------------------------------------
__global__ void __launch_bounds__(256, 2)
gemm_tc64_kernel(const __nv_bfloat16* __restrict__ A2g, const __nv_bfloat16* __restrict__ B2g,
                 float* __restrict__ Cg, int Kf, int Kloc,
                 long sA, long sB, long sC, long pC)
{
    extern __shared__ char smem[];
    const uint32_t sbase = smem_u32(smem);
    const int tid = threadIdx.x;
    const int wid = tid >> 5, L = tid & 31;
    const int bm = blockIdx.x * 128;
    const int warp_m = wid & 3, warp_n = wid >> 2;
    const long koff = (long)blockIdx.y * Kloc;
    const __nv_bfloat16* A2 = A2g + (long)blockIdx.z * sA;
    const __nv_bfloat16* B2 = B2g + (long)blockIdx.z * sB;
    float* C = Cg + (long)blockIdx.z * sC + (long)blockIdx.y * pC;
    const size_t ld2 = 2 * (size_t)Kf;
    const int CPP = Kloc / KC;
    const int NCH = 3 * CPP;

    const int lrow = tid >> 3;
    const int lc16 = tid & 7;
    const int scol = (lc16 * 16) ^ ((lrow & 7) << 4);

    auto issue = [&](int c) {
        const int s = c % NST;
        const int p = c / CPP;
        const int kc = (c - p * CPP) * KC;
        const long aoff = ((p == 2) ? Kf : 0) + koff + kc;
        const long boff = ((p == 1) ? Kf : 0) + koff + kc;
        const __nv_bfloat16* Ap = A2 + (size_t)bm * ld2 + aoff + lc16 * 8;
        const __nv_bfloat16* Bp = B2 + boff + lc16 * 8;
        const uint32_t stA = sbase + s * 24576;
        const uint32_t stB = stA + 16384;
#pragma unroll
        for (int j = 0; j < 4; j++) {
            const int r = lrow + j * 32;
            cp16(stA + r * 128 + scol, Ap + (size_t)r * ld2);
        }
#pragma unroll
        for (int j = 0; j < 2; j++) {
            const int r = lrow + j * 32;
            cp16(stB + r * 128 + scol, Bp + (size_t)r * ld2);
        }
        asm volatile("cp.async.commit_group;" ::: "memory");
    };

    float acc[2][4][4];
#pragma unroll
    for (int i = 0; i < 2; i++)
#pragma unroll
        for (int j = 0; j < 4; j++)
#pragma unroll
            for (int k = 0; k < 4; k++) acc[i][j][k] = 0.f;

    issue(0);
    issue(1);

    const int lrow16 = L & 15;
    const int lhi = (L >> 4) * 16;
    const int lxor = (L & 7) << 4;
    const uint32_t a_row = (uint32_t)(warp_m * 32 + lrow16) * 128;
    const uint32_t b_row = (uint32_t)(warp_n * 32 + lrow16) * 128;

    for (int c = 0; c < NCH; c++) {
        if (c + 1 < NCH) asm volatile("cp.async.wait_group 1;" ::: "memory");
        else             asm volatile("cp.async.wait_group 0;" ::: "memory");
        __syncthreads();
        if (c + 2 < NCH) issue(c + 2);
        const int s = c % NST;
        const uint32_t stA = sbase + s * 24576;
        const uint32_t stB = stA + 16384;
#pragma unroll
        for (int ks = 0; ks < 4; ks++) {
            uint32_t af[2][4], bf[2][4];
            const uint32_t coff = (uint32_t)((ks * 32 + lhi) ^ lxor);
#pragma unroll
            for (int mf = 0; mf < 2; mf++)
                ldm4(af[mf], stA + a_row + mf * 2048 + coff);
#pragma unroll
            for (int nf = 0; nf < 2; nf++)
                ldm4(bf[nf], stB + b_row + nf * 2048 + coff);
#pragma unroll
            for (int mf = 0; mf < 2; mf++)
#pragma unroll
                for (int ng = 0; ng < 4; ng++)
                    mma16816(acc[mf][ng], af[mf],
                             bf[ng >> 1][ng & 1], bf[ng >> 1][(ng & 1) + 2]);
        }
    }
    __syncthreads();

    const int q = L >> 2, t2 = (L & 3) * 2;
#pragma unroll
    for (int mf = 0; mf < 2; mf++) {
        const int r0 = bm + warp_m * 32 + mf * 16 + q;
        const int r1 = r0 + 8;
#pragma unroll
        for (int ng = 0; ng < 4; ng++) {
            const int col = warp_n * 32 + ng * 8 + t2;
            *(float2*)(C + (size_t)r0 * 64 + col) = make_float2(acc[mf][ng][0], acc[mf][ng][1]);
            *(float2*)(C + (size_t)r1 * 64 + col) = make_float2(acc[mf][ng][2], acc[mf][ng][3]);
        }
    }
}

// ------------------------------------------------------------------
// LayerNorm (biased var) + ReLU over rows of g_xm, writing bf16 hi|lo
// directly into g_gate2 [row][2*CNC] (xmD2 layout).
// ------------------------------------------------------------------
__global__ void __launch_bounds__(256) ln_relu_kernel(
    const float* __restrict__ ln_g, const float* __restrict__ ln_b)
{
    const int row = blockIdx.x;
    const float* p = g_xm + (size_t)row * CNC;
    __nv_bfloat16* o = g_gate2 + (size_t)row * 2 * CNC;
    const int tid = threadIdx.x;
    float v[8];
    float s = 0.f, s2 = 0.f;
#pragma unroll
    for (int j = 0; j < 8; j++) {
        const float t = p[tid + j * 256];
        v[j] = t; s += t; s2 += t * t;
    }
#pragma unroll
    for (int o2 = 16; o2; o2 >>= 1) {
        s  += __shfl_xor_sync(0xffffffffu, s,  o2);
        s2 += __shfl_xor_sync(0xffffffffu, s2, o2);
    }
    __shared__ float ss[8], ss2[8], sh[2];
    if ((tid & 31) == 0) { ss[tid >> 5] = s; ss2[tid >> 5] = s2; }
    __syncthreads();
    if (tid == 0) {
        float t = 0.f, t2 = 0.f;
#pragma unroll
        for (int i = 0; i < 8; i++) { t += ss[i]; t2 += ss2[i]; }
        const float mu  = t * (1.0f / CNC);
        const float var = t2 * (1.0f / CNC) - mu * mu;
        sh[0] = mu; sh[1] = rsqrtf(var + CLN_EPS);
    }
    __syncthreads();
    const float mu = sh[0], rs = sh[1];
#pragma unroll
    for (int j = 0; j < 8; j++) {
        const int c = tid + j * 256;
        const float y = (v[j] - mu) * rs * ln_g[c] + ln_b[c];
        const float r = fmaxf(y, 0.f);
        const __nv_bfloat16 h = __float2bfloat16(r);
        o[c]       = h;
        o[CNC + c] = __float2bfloat16(r - __bfloat162float(h));
    }
}

// ------------------------------------------------------------------
// Broadcast bases0 (1, S, R) -> g_bases (B, S, R)
// ------------------------------------------------------------------
__global__ void __launch_bounds__(256) bcast_bases_kernel(const float* __restrict__ b0)
{
    const int i = blockIdx.x * 256 + threadIdx.x;
    g_bases[i] = b0[i & (CS * CR - 1)];
}

// ------------------------------------------------------------------
// TN skinny GEMM (SIMT, Gram matrices only)
// ------------------------------------------------------------------
__global__ void __launch_bounds__(256) gemm_tn64_kernel(
    const float* __restrict__ A, const float* __restrict__ Bv, float* __restrict__ C,
    int M, int lda, int Ktot, int ksplit,
    long strideA, long strideB, long strideC, long partStride)
{
    const int b = blockIdx.z;
    const int Kloc = Ktot / ksplit;
    const long koff = (long)blockIdx.y * Kloc;
    const float* Ab = A + (long)b * strideA + koff * lda;
    const float* Bb = Bv + (long)b * strideB + koff * 64;
    float* Cb = C + (long)b * strideC + (long)blockIdx.y * partStride;
    const int bm = blockIdx.x * 128;

    __shared__ float Asm[16][128];
    __shared__ float Bsm[16][64];
    const int tid = threadIdx.x;
    const int tm = tid & 31, tr = tid >> 5;
    float acc[4][8];
#pragma unroll
    for (int i = 0; i < 4; i++)
#pragma unroll
        for (int j = 0; j < 8; j++) acc[i][j] = 0.f;

    for (int k0 = 0; k0 < Kloc; k0 += 16) {
#pragma unroll
        for (int i = 0; i < 8; i++) {
            const int idx = tid + i * 256;
            const int kk = idx >> 7, mm = idx & 127;
            const int gm = bm + mm;
            Asm[kk][mm] = (gm < M) ? Ab[(long)(k0 + kk) * lda + gm] : 0.f;
        }
#pragma unroll
        for (int i = 0; i < 4; i++) {
            const int idx = tid + i * 256;
            const int kk = idx >> 6, rr = idx & 63;
            Bsm[kk][rr] = Bb[(long)(k0 + kk) * 64 + rr];
        }
        __syncthreads();
#pragma unroll
        for (int kk = 0; kk < 16; kk++) {
            float ra[4], rb[8];
            *(float4*)ra      = *(const float4*)&Asm[kk][tm * 4];
            *(float4*)&rb[0]  = *(const float4*)&Bsm[kk][tr * 8];
            *(float4*)&rb[4]  = *(const float4*)&Bsm[kk][tr * 8 + 4];
#pragma unroll
            for (int i = 0; i < 4; i++)
#pragma unroll
                for (int j = 0; j < 8; j++)
                    acc[i][j] = fmaf(ra[i], rb[j], acc[i][j]);
        }
        __syncthreads();
    }
#pragma unroll
    for (int i = 0; i < 4; i++) {
        const int m = bm + tm * 4 + i;
        if (m < M) {
#pragma unroll
            for (int j = 0; j < 8; j++)
                Cb[(long)m * 64 + tr * 8 + j] = acc[i][j];
        }
    }
}

// ------------------------------------------------------------------
// NN skinny GEMM: multiplicative NMF updates (K=64 only).
// Num is a sum of numPartN partials (stride numPartStride).
// ------------------------------------------------------------------
__global__ void __launch_bounds__(256) gemm_nn64_kernel(
    const float* __restrict__ A, const float* __restrict__ Bv,
    const float* __restrict__ Num, float* __restrict__ Cout,
    int lda, int K, int npart, long partStride,
    long strideA, long strideB, long strideC, long strideNum,
    int numPartN, long numPartStride)
{
    const int b = blockIdx.z;
    const float* Ab = A + (long)b * strideA;
    const float* Bb = Bv + (long)b * strideB;
    float* Cb = Cout + (long)b * strideC;
    const float* Nb = Num + (long)b * strideNum;
    const int bm = blockIdx.x * 128;

    __shared__ float Asm[16][132];
    __shared__ float Bsm[16][64];
    const int tid = threadIdx.x;
    const int tm = tid & 31, tr = tid >> 5;
    float acc[4][8];
#pragma unroll
    for (int i = 0; i < 4; i++)
#pragma unroll
        for (int j = 0; j < 8; j++) acc[i][j] = 0.f;

    for (int k0 = 0; k0 < K; k0 += 16) {
#pragma unroll
        for (int i = 0; i < 8; i++) {
            const int idx = tid + i * 256;
            const int mm = idx >> 4, kk = idx & 15;
            Asm[kk][mm] = Ab[(long)(bm + mm) * lda + k0 + kk];
        }
#pragma unroll
        for (int i = 0; i < 4; i++) {
            const int idx = tid + i * 256;
            const int kk = idx >> 6, rr = idx & 63;
            float v = 0.f;
            for (int p = 0; p < npart; p++)
                v += Bb[(long)p * partStride + (long)(k0 + kk) * 64 + rr];
            Bsm[kk][rr] = v;
        }
        __syncthreads();
#pragma unroll
        for (int kk = 0; kk < 16; kk++) {
            float ra[4], rb[8];
            *(float4*)ra     = *(const float4*)&Asm[kk][tm * 4];
            *(float4*)&rb[0] = *(const float4*)&Bsm[kk][tr * 8];
            *(float4*)&rb[4] = *(const float4*)&Bsm[kk][tr * 8 + 4];
#pragma unroll
            for (int i = 0; i < 4; i++)
#pragma unroll
                for (int j = 0; j < 8; j++)
                    acc[i][j] = fmaf(ra[i], rb[j], acc[i][j]);
        }
        __syncthreads();
    }
#pragma unroll
    for (int i = 0; i < 4; i++) {
        const int m = bm + tm * 4 + i;
#pragma unroll
        for (int j = 0; j < 8; j++) {
            const int r = tr * 8 + j;
            const long idx = (long)m * 64 + r;
            float nv = 0.f;
            for (int q = 0; q < numPartN; q++)
                nv += Nb[q * numPartStride + idx];
            Cb[idx] = Cb[idx] * nv / (acc[i][j] + NMF_EPS);
        }
    }
}

// ------------------------------------------------------------------
// Row softmax over R=64 on sum of NSPL partials of g_numn -> g_coef.
// ------------------------------------------------------------------
__global__ void __launch_bounds__(256) softmax64_kernel()
{
    const int row = blockIdx.x * 8 + (threadIdx.x >> 5);
    const int l = threadIdx.x & 31;
    const float* src = g_numn + (size_t)row * 64;
    float a = src[l] + src[PARTN + l];
    float c = src[l + 32] + src[PARTN + l + 32];
    float mx = fmaxf(a, c);
#pragma unroll
    for (int o = 16; o; o >>= 1) mx = fmaxf(mx, __shfl_xor_sync(0xffffffffu, mx, o));
    a = expf(a - mx); c = expf(c - mx);
    float s = a + c;
#pragma unroll
    for (int o = 16; o; o >>= 1) s += __shfl_xor_sync(0xffffffffu, s, o);
    const float inv = 1.f / s;
    float* dst = g_coef + (size_t)row * 64;
    dst[l] = a * inv; dst[l + 32] = c * inv;
}

// ------------------------------------------------------------------
// Reconstruct + gate, writing bf16 hi|lo directly into g_gate2:
// gate2[b,d, :] = split( z1[b,d,n] * sum_r bases[b,d,r]*coef[b,n,r] )
// ------------------------------------------------------------------
__global__ void __launch_bounds__(256) recon_gate_kernel()
{
    const int b  = blockIdx.z;
    const int bd = blockIdx.y * 64;
    const int bn = blockIdx.x * 64;
    const float* bas = g_bases + (size_t)b * CS * CR;
    const float* cof = g_coef  + (size_t)b * CNC * CR;
    __shared__ float Bas[CR][68];
    __shared__ float Cof[CR][68];
    const int tid = threadIdx.x;
#pragma unroll
    for (int i = 0; i < 16; i++) {
        const int idx = tid + i * 256;
        const int dd = idx >> 6, rr = idx & 63;
        Bas[rr][dd] = bas[(size_t)(bd + dd) * CR + rr];
    }
#pragma unroll
    for (int i = 0; i < 16; i++) {
        const int idx = tid + i * 256;
        const int nn = idx >> 6, rr = idx & 63;
        Cof[rr][nn] = cof[(size_t)(bn + nn) * CR + rr];
    }
    __syncthreads();
    const int td = tid >> 4, tn = tid & 15;
    float acc[4][4];
#pragma unroll
    for (int i = 0; i < 4; i++)
#pragma unroll
        for (int j = 0; j < 4; j++) acc[i][j] = 0.f;
#pragma unroll
    for (int r = 0; r < CR; r++) {
        float ra[4], rb[4];
        *(float4*)ra = *(const float4*)&Bas[r][td * 4];
        *(float4*)rb = *(const float4*)&Cof[r][tn * 4];
#pragma unroll
        for (int i = 0; i < 4; i++)
#pragma unroll
            for (int j = 0; j < 4; j++)
                acc[i][j] = fmaf(ra[i], rb[j], acc[i][j]);
    }
#pragma unroll
    for (int i = 0; i < 4; i++) {
        const int d = bd + td * 4 + i;
        const size_t zoff = ((size_t)b * CS + d) * CNC;
        __nv_bfloat16* orow = g_gate2 + ((size_t)b * CS + d) * 2 * CNC;
#pragma unroll
        for (int j = 0; j < 4; j++) {
            const int n = bn + tn * 4 + j;
            const float v = g_z1[zoff + n] * acc[i][j];
            const __nv_bfloat16 h = __float2bfloat16(v);
            orow[n]       = h;
            orow[CNC + n] = __float2bfloat16(v - __bfloat162float(h));
        }
    }
}

// ------------------------------------------------------------------
// Launch sequence
// ------------------------------------------------------------------
extern "C" void kernel_launch(void* const* d_in, const int* in_sizes, int n_in,
                              void* d_out, int out_size)
{
    const float* x    = (const float*)d_in[0];
    const float* U_w  = (const float*)d_in[1];
    const float* U_b  = (const float*)d_in[2];
    const float* ln_g = (const float*)d_in[3];
    const float* ln_b = (const float*)d_in[4];
    const float* bas0 = (const float*)d_in[5];
    const float* V_w  = (const float*)d_in[6];
    const float* V_b  = (const float*)d_in[7];
    float* out = (float*)d_out;

    float *z1, *xm, *coef, *bases, *numn, *numd, *btb, *ctc;
    __nv_bfloat16 *xh2, *uw2, *gate2, *vw2, *xmT2, *basT2, *cofT2;
    cudaGetSymbolAddress((void**)&z1,    g_z1);
    cudaGetSymbolAddress((void**)&xm,    g_xm);
    cudaGetSymbolAddress((void**)&coef,  g_coef);
    cudaGetSymbolAddress((void**)&bases, g_bases);
    cudaGetSymbolAddress((void**)&numn,  g_numn);
    cudaGetSymbolAddress((void**)&numd,  g_numd);
    cudaGetSymbolAddress((void**)&btb,   g_btb);
    cudaGetSymbolAddress((void**)&ctc,   g_ctc);
    cudaGetSymbolAddress((void**)&xh2,   g_xh2);
    cudaGetSymbolAddress((void**)&uw2,   g_uw2);
    cudaGetSymbolAddress((void**)&gate2, g_gate2);
    cudaGetSymbolAddress((void**)&vw2,   g_vw2);
    cudaGetSymbolAddress((void**)&xmT2,  g_xmT2);
    cudaGetSymbolAddress((void**)&basT2, g_basT2);
    cudaGetSymbolAddress((void**)&cofT2, g_cofT2);

    cudaFuncSetAttribute(gemm_tc_kernel<0>, cudaFuncAttributeMaxDynamicSharedMemorySize, TCSMEM);
    cudaFuncSetAttribute(gemm_tc_kernel<1>, cudaFuncAttributeMaxDynamicSharedMemorySize, TCSMEM);
    cudaFuncSetAttribute(gemm_tc64_kernel, cudaFuncAttributeMaxDynamicSharedMemorySize, TC64SMEM);

    const long S_BAS = (long)CS * CR;
    const long S_CO  = (long)CNC * CR;
    const long S_GRAM = (long)GSPLIT * CR * CR;
    const long SA_T = (long)CNC * 2 * CS;   // xmT2 per-batch
    const long SB_T = (long)CR * 2 * CS;    // basT2 per-batch
    const long SA_D = (long)CS * 2 * CNC;   // gate2 (xmD2) per-batch
    const long SB_D = (long)CR * 2 * CNC;   // cofT2 per-batch

    auto pack_basT = [&]() {
        transpack_kernel<<<dim3(CR / 32, CS / 32, CB), dim3(32, 8)>>>(
            bases, basT2, CS, CR, S_BAS, SB_T);
    };
    auto tc_numn = [&]() {
        gemm_tc64_kernel<<<dim3(CNC / 128, NSPL, CB), 256, TC64SMEM>>>(
            xmT2, basT2, numn, CS, CS / NSPL, SA_T, SB_T, S_CO, PARTN);
    };

    // 0) split-pack x, U_w, V_w to bf16 hi|lo
    pack_kernel<<<(CBS * CF / 4) / 256, 256>>>(x, xh2, 10, CBS * CF / 4);
    pack_kernel<<<(CFFN * CF / 4) / 256, 256>>>(U_w, uw2, 10, CFFN * CF / 4);
    pack_kernel<<<(CF * CNC / 4) / 256, 256>>>(V_w, vw2, 11, CF * CNC / 4);

    // 1) h = gelu(x @ U_w^T + U_b), split into z1 / xm (z2 pre-LN)
    gemm_tc_kernel<0><<<dim3(CFFN / 128, CBS / 128), 256, TCSMEM>>>(
        xh2, uw2, U_b, z1, xm, CF, CFFN);

    // 2) LayerNorm + ReLU, writing packed hi|lo xmD2 directly into gate2
    ln_relu_kernel<<<CBS, 256>>>(ln_g, ln_b);

    // 3) broadcast bases; build xm^T packed layout from gate2
    bcast_bases_kernel<<<(CB * CS * CR) / 256, 256>>>(bas0);
    transpack_bf_kernel<<<dim3(CNC / 32, CS / 32, CB), dim3(32, 8)>>>(
        gate2, xmT2, CS, CNC, SA_D, SA_T);

    // 4) coef = softmax(xm^T @ bases)
    pack_basT();
    tc_numn();
    softmax64_kernel<<<(CB * CNC) / 8, 256>>>();

    // 5) 6 NMF steps (numn from init reused at it=0: bases unchanged)
    for (int it = 0; it < NSTEPS; it++) {
        if (it > 0) { pack_basT(); tc_numn(); }
        gemm_tn64_kernel<<<dim3(1, GSPLIT, CB), 256>>>(
            bases, bases, btb, CR, CR, CS, GSPLIT, S_BAS, S_BAS, S_GRAM, (long)CR * CR);
        gemm_nn64_kernel<<<dim3(CNC / 128, 1, CB), 256>>>(
            coef, btb, numn, coef, CR, CR, GSPLIT, (long)CR * CR,
            S_CO, S_GRAM, S_CO, S_CO, NSPL, PARTN);
        transpack_kernel<<<dim3(CR / 32, CNC / 32, CB), dim3(32, 8)>>>(
            coef, cofT2, CNC, CR, S_CO, SB_D);
        gemm_tc64_kernel<<<dim3(CS / 128, DSPL, CB), 256, TC64SMEM>>>(
            gate2, cofT2, numd, CNC, CNC / DSPL, SA_D, SB_D, S_BAS, PARTD);
        gemm_tn64_kernel<<<dim3(1, GSPLIT, CB), 256>>>(
            coef, coef, ctc, CR, CR, CNC, GSPLIT, S_CO, S_CO, S_GRAM, (long)CR * CR);
        gemm_nn64_kernel<<<dim3(CS / 128, 1, CB), 256>>>(
            bases, ctc, numd, bases, CR, CR, GSPLIT, (long)CR * CR,
            S_BAS, S_GRAM, S_BAS, S_BAS, DSPL, PARTD);
    }

    // 6) final coef update (compute_coef)
    pack_basT();
    tc_numn();
    gemm_tn64_kernel<<<dim3(1, GSPLIT, CB), 256>>>(
        bases, bases, btb, CR, CR, CS, GSPLIT, S_BAS, S_BAS, S_GRAM, (long)CR * CR);
    gemm_nn64_kernel<<<dim3(CNC / 128, 1, CB), 256>>>(
        coef, btb, numn, coef, CR, CR, GSPLIT, (long)CR * CR,
        S_CO, S_GRAM, S_CO, S_CO, NSPL, PARTN);

    // 7) gated reconstruction, writing packed hi|lo directly into gate2
    recon_gate_kernel<<<dim3(CNC / 64, CS / 64, CB), 256>>>();

    // 8) out = gated @ V_w^T + V_b
    gemm_tc_kernel<1><<<dim3(CF / 128, CBS / 128), 256, TCSMEM>>>(
        gate2, vw2, V_b, out, nullptr, CNC, CF);
}

// round 17
// speedup vs baseline: 1.1418x; 1.1418x over previous
#include <cuda_runtime.h>
#include <cuda_bf16.h>
#include <math.h>
#include <stdint.h>

// Problem constants
#define CB 8
#define CS 1024
#define CF 1024
#define CFFN 4096
#define CNC 2048
#define CR 64
#define CBS (CB*CS)          // 8192
#define NSTEPS 6
#define NMF_EPS 1e-6f
#define CLN_EPS 1e-5f
#define GSPLIT 8             // K-split for initial btb Gram
#define CPARTS 16            // ctc partials (= CNC/128 CTAs of coef update)
#define BPARTS 8             // btb partials (= CS/128 CTAs of bases update)
#define NSPL 2               // K-split for numn tensor GEMM
#define DSPL 4               // K-split for numd tensor GEMM

// tensor GEMM config
#define NST 3                // cp.async pipeline stages
#define KC 64                // bf16 K elements per chunk (128B rows, SW128)
#define TCSMEM (NST * 32768)
#define TC64SMEM (NST * 24576)

// ------------------------------------------------------------------
// Device scratch (allocation-free rule: __device__ globals)
// ------------------------------------------------------------------
__device__ float g_z1[(size_t)CBS * CNC];            // 64 MB
__device__ float g_xm[(size_t)CBS * CNC];            // 64 MB (z2 pre-LN only)
__device__ float g_coef [CB * CNC * CR];
__device__ float g_bases[CB * CS  * CR];
__device__ float g_numn [NSPL * CB * CNC * CR];      // 2 K-partials
__device__ float g_numd [DSPL * CB * CS  * CR];      // 4 K-partials
__device__ float g_btb  [BPARTS * CB * CR * CR];     // 8 partials
__device__ float g_ctc  [CPARTS * CB * CR * CR];     // 16 partials
// split-bf16 packed operands: [rows][2K] = (hi | lo)
__device__ __nv_bfloat16 g_xh2  [(size_t)CBS * 2 * CF];    // 32 MB
__device__ __nv_bfloat16 g_uw2  [(size_t)CFFN * 2 * CF];   // 16 MB
__device__ __nv_bfloat16 g_gate2[(size_t)CBS * 2 * CNC];   // 64 MB (xmD2, then gated)
__device__ __nv_bfloat16 g_vw2  [(size_t)CF * 2 * CNC];    // 8 MB
// NMF tensor-core operands
__device__ __nv_bfloat16 g_xmT2 [(size_t)CB * CNC * 2 * CS];  // 64 MB: xm^T hi|lo [n][2D]
__device__ __nv_bfloat16 g_basT2[(size_t)CB * CR * 2 * CS];   // 2 MB
__device__ __nv_bfloat16 g_cofT2[(size_t)CB * CR * 2 * CNC];  // 4 MB

#define PARTN ((long)CB * CNC * CR)
#define PARTD ((long)CB * CS * CR)

__device__ __forceinline__ float gelu_exact(float v) {
    return 0.5f * v * (1.0f + erff(v * 0.70710678118654752440f));
}

// ------------------------------------------------------------------
// PTX helpers (all baseline sm_80+ instructions; no tcgen05)
// ------------------------------------------------------------------
__device__ __forceinline__ uint32_t smem_u32(const void* p) {
    uint32_t a;
    asm("{ .reg .u64 t; cvta.to.shared.u64 t, %1; cvt.u32.u64 %0, t; }" : "=r"(a) : "l"(p));
    return a;
}
__device__ __forceinline__ void cp16(uint32_t dst, const void* src) {
    asm volatile("cp.async.cg.shared.global [%0], [%1], 16;" :: "r"(dst), "l"(src));
}
__device__ __forceinline__ void ldm4(uint32_t* r, uint32_t addr) {
    asm volatile("ldmatrix.sync.aligned.m8n8.x4.shared.b16 {%0,%1,%2,%3}, [%4];"
                 : "=r"(r[0]), "=r"(r[1]), "=r"(r[2]), "=r"(r[3]) : "r"(addr));
}
__device__ __forceinline__ void mma16816(float* d, const uint32_t* a, uint32_t b0, uint32_t b1) {
    asm volatile("mma.sync.aligned.m16n8k16.row.col.f32.bf16.bf16.f32 "
                 "{%0,%1,%2,%3}, {%4,%5,%6,%7}, {%8,%9}, {%0,%1,%2,%3};"
                 : "+f"(d[0]), "+f"(d[1]), "+f"(d[2]), "+f"(d[3])
                 : "r"(a[0]), "r"(a[1]), "r"(a[2]), "r"(a[3]), "r"(b0), "r"(b1));
}

// ------------------------------------------------------------------
// Split pack: fp32 [rows][K] -> bf16 [rows][2K] = hi | lo.  K = 1<<kb.
// ------------------------------------------------------------------
__device__ __forceinline__ uint32_t bpair(float a, float b) {
    __nv_bfloat162 t = __floats2bfloat162_rn(a, b);
    return *reinterpret_cast<uint32_t*>(&t);
}
__global__ void __launch_bounds__(256) pack_kernel(
    const float* __restrict__ in, __nv_bfloat16* __restrict__ out, int kb, int total4)
{
    const int i = blockIdx.x * 256 + threadIdx.x;
    if (i >= total4) return;
    const int base = i << 2;
    const int K = 1 << kb;
    const int m = base >> kb;
    const int k = base & (K - 1);
    const float4 v = *(const float4*)(in + (size_t)base);
    const float h0 = __bfloat162float(__float2bfloat16(v.x));
    const float h1 = __bfloat162float(__float2bfloat16(v.y));
    const float h2 = __bfloat162float(__float2bfloat16(v.z));
    const float h3 = __bfloat162float(__float2bfloat16(v.w));
    uint2 hv, lv;
    hv.x = bpair(v.x, v.y);           hv.y = bpair(v.z, v.w);
    lv.x = bpair(v.x - h0, v.y - h1); lv.y = bpair(v.z - h2, v.w - h3);
    __nv_bfloat16* o = out + ((size_t)m << (kb + 1)) + k;
    *(uint2*)o       = hv;
    *(uint2*)(o + K) = lv;
}

// ------------------------------------------------------------------
// Transpose + split pack, bf16-pair source: src [D][2N] hi|lo -> dst [N][2D] hi|lo
// ------------------------------------------------------------------
__global__ void __launch_bounds__(256) transpack_bf_kernel(
    const __nv_bfloat16* __restrict__ src, __nv_bfloat16* __restrict__ dst,
    int D, int N, long sStride, long dStride)
{
    __shared__ float t[32][33];
    const __nv_bfloat16* s = src + (long)blockIdx.z * sStride;
    __nv_bfloat16* d = dst + (long)blockIdx.z * dStride;
    const int n0 = blockIdx.x * 32, d0 = blockIdx.y * 32;
#pragma unroll
    for (int j = threadIdx.y; j < 32; j += 8) {
        const size_t row = (size_t)(d0 + j) * 2 * N;
        t[j][threadIdx.x] = __bfloat162float(s[row + n0 + threadIdx.x])
                          + __bfloat162float(s[row + N + n0 + threadIdx.x]);
    }
    __syncthreads();
#pragma unroll
    for (int j = threadIdx.y; j < 32; j += 8) {
        const int n = n0 + j;
        const int dd = d0 + threadIdx.x;
        const float v = t[threadIdx.x][j];
        const __nv_bfloat16 h = __float2bfloat16(v);
        __nv_bfloat16* row = d + (size_t)n * 2 * D;
        row[dd]     = h;
        row[D + dd] = __float2bfloat16(v - __bfloat162float(h));
    }
}

// ------------------------------------------------------------------
// Tensor-core split-bf16 NT GEMM: C[M,N] = A[M,K] * B[N,K]^T + bias
// (fp32 via 3 bf16 passes). 128x128 CTA tile, 8 warps, BK=64, 3-stage ring.
// MODE 0: gelu epilogue, split store z1/xm.  MODE 1: bias store to C0.
// ------------------------------------------------------------------
template <int MODE>
__global__ void __launch_bounds__(256, 2)
gemm_tc_kernel(const __nv_bfloat16* __restrict__ A2, const __nv_bfloat16* __restrict__ B2,
               const float* __restrict__ bias, float* __restrict__ C0, float* __restrict__ C1,
               int Kf, int Nfull)
{
    extern __shared__ char smem[];
    const uint32_t sbase = smem_u32(smem);
    const int tid = threadIdx.x;
    const int wid = tid >> 5, L = tid & 31;
    const int bm = blockIdx.y * 128, bn = blockIdx.x * 128;
    const int warp_m = wid & 3, warp_n = wid >> 2;
    const size_t ld2 = 2 * (size_t)Kf;
    const int CPP = Kf / KC;
    const int NCH = 3 * CPP;

    const int lrow = tid >> 3;
    const int lc16 = tid & 7;
    const int scol = (lc16 * 16) ^ ((lrow & 7) << 4);

    auto issue = [&](int c) {
        const int s = c % NST;
        const int p = c / CPP;
        const int kc = (c - p * CPP) * KC;
        const int aoff = (p == 2) ? Kf : 0;
        const int boff = (p == 1) ? Kf : 0;
        const __nv_bfloat16* Ap = A2 + (size_t)bm * ld2 + aoff + kc + lc16 * 8;
        const __nv_bfloat16* Bp = B2 + (size_t)bn * ld2 + boff + kc + lc16 * 8;
        const uint32_t stA = sbase + s * 32768;
        const uint32_t stB = stA + 16384;
#pragma unroll
        for (int j = 0; j < 4; j++) {
            const int r = lrow + j * 32;
            cp16(stA + r * 128 + scol, Ap + (size_t)r * ld2);
            cp16(stB + r * 128 + scol, Bp + (size_t)r * ld2);
        }
        asm volatile("cp.async.commit_group;" ::: "memory");
    };

    float acc[2][8][4];
#pragma unroll
    for (int i = 0; i < 2; i++)
#pragma unroll
        for (int j = 0; j < 8; j++)
#pragma unroll
            for (int k = 0; k < 4; k++) acc[i][j][k] = 0.f;

    issue(0);
    issue(1);

    const int lrow16 = L & 15;
    const int lhi = (L >> 4) * 16;
    const int lxor = (L & 7) << 4;
    const uint32_t a_row = (uint32_t)(warp_m * 32 + lrow16) * 128;
    const uint32_t b_row = (uint32_t)(warp_n * 64 + lrow16) * 128;

    for (int c = 0; c < NCH; c++) {
        if (c + 1 < NCH) asm volatile("cp.async.wait_group 1;" ::: "memory");
        else             asm volatile("cp.async.wait_group 0;" ::: "memory");
        __syncthreads();
        if (c + 2 < NCH) issue(c + 2);
        const int s = c % NST;
        const uint32_t stA = sbase + s * 32768;
        const uint32_t stB = stA + 16384;
#pragma unroll
        for (int ks = 0; ks < 4; ks++) {
            uint32_t af[2][4], bf[4][4];
            const uint32_t coff = (uint32_t)((ks * 32 + lhi) ^ lxor);
#pragma unroll
            for (int mf = 0; mf < 2; mf++)
                ldm4(af[mf], stA + a_row + mf * 2048 + coff);
#pragma unroll
            for (int nf = 0; nf < 4; nf++)
                ldm4(bf[nf], stB + b_row + nf * 2048 + coff);
#pragma unroll
            for (int mf = 0; mf < 2; mf++)
#pragma unroll
                for (int ng = 0; ng < 8; ng++)
                    mma16816(acc[mf][ng], af[mf],
                             bf[ng >> 1][ng & 1], bf[ng >> 1][(ng & 1) + 2]);
        }
    }
    __syncthreads();

    const int q = L >> 2, t2 = (L & 3) * 2;
#pragma unroll
    for (int ng = 0; ng < 8; ng++) {
        const int col = bn + warp_n * 64 + ng * 8 + t2;
        const float b0v = __ldg(bias + col), b1v = __ldg(bias + col + 1);
#pragma unroll
        for (int mf = 0; mf < 2; mf++) {
            const int r0 = bm + warp_m * 32 + mf * 16 + q;
            const int r1 = r0 + 8;
            float v00 = acc[mf][ng][0] + b0v, v01 = acc[mf][ng][1] + b1v;
            float v10 = acc[mf][ng][2] + b0v, v11 = acc[mf][ng][3] + b1v;
            if (MODE == 0) {
                v00 = gelu_exact(v00); v01 = gelu_exact(v01);
                v10 = gelu_exact(v10); v11 = gelu_exact(v11);
                if (col < CNC) {
                    *(float2*)(C0 + (size_t)r0 * CNC + col) = make_float2(v00, v01);
                    *(float2*)(C0 + (size_t)r1 * CNC + col) = make_float2(v10, v11);
                } else {
                    *(float2*)(C1 + (size_t)r0 * CNC + (col - CNC)) = make_float2(v00, v01);
                    *(float2*)(C1 + (size_t)r1 * CNC + (col - CNC)) = make_float2(v10, v11);
                }
            } else {
                *(float2*)(C0 + (size_t)r0 * Nfull + col) = make_float2(v00, v01);
                *(float2*)(C0 + (size_t)r1 * Nfull + col) = make_float2(v10, v11);
            }
        }
    }
}

// ------------------------------------------------------------------
// Skinny tensor-core split-bf16 NT GEMM with K-split:
// C_part[y][M,64] = A[M, koff:koff+Kloc] * B[64, koff:koff+Kloc]^T
// ------------------------------------------------------------------
__global__ void __launch_bounds__(256, 2)
gemm_tc64_kernel(const __nv_bfloat16* __restrict__ A2g, const __nv_bfloat16* __restrict__ B2g,
                 float* __restrict__ Cg, int Kf, int Kloc,
                 long sA, long sB, long sC, long pC)
{
    extern __shared__ char smem[];
    const uint32_t sbase = smem_u32(smem);
    const int tid = threadIdx.x;
    const int wid = tid >> 5, L = tid & 31;
    const int bm = blockIdx.x * 128;
    const int warp_m = wid & 3, warp_n = wid >> 2;
    const long koff = (long)blockIdx.y * Kloc;
    const __nv_bfloat16* A2 = A2g + (long)blockIdx.z * sA;
    const __nv_bfloat16* B2 = B2g + (long)blockIdx.z * sB;
    float* C = Cg + (long)blockIdx.z * sC + (long)blockIdx.y * pC;
    const size_t ld2 = 2 * (size_t)Kf;
    const int CPP = Kloc / KC;
    const int NCH = 3 * CPP;

    const int lrow = tid >> 3;
    const int lc16 = tid & 7;
    const int scol = (lc16 * 16) ^ ((lrow & 7) << 4);

    auto issue = [&](int c) {
        const int s = c % NST;
        const int p = c / CPP;
        const int kc = (c - p * CPP) * KC;
        const long aoff = ((p == 2) ? Kf : 0) + koff + kc;
        const long boff = ((p == 1) ? Kf : 0) + koff + kc;
        const __nv_bfloat16* Ap = A2 + (size_t)bm * ld2 + aoff + lc16 * 8;
        const __nv_bfloat16* Bp = B2 + boff + lc16 * 8;
        const uint32_t stA = sbase + s * 24576;
        const uint32_t stB = stA + 16384;
#pragma unroll
        for (int j = 0; j < 4; j++) {
            const int r = lrow + j * 32;
            cp16(stA + r * 128 + scol, Ap + (size_t)r * ld2);
        }
#pragma unroll
        for (int j = 0; j < 2; j++) {
            const int r = lrow + j * 32;
            cp16(stB + r * 128 + scol, Bp + (size_t)r * ld2);
        }
        asm volatile("cp.async.commit_group;" ::: "memory");
    };

    float acc[2][4][4];
#pragma unroll
    for (int i = 0; i < 2; i++)
#pragma unroll
        for (int j = 0; j < 4; j++)
#pragma unroll
            for (int k = 0; k < 4; k++) acc[i][j][k] = 0.f;

    issue(0);
    issue(1);

    const int lrow16 = L & 15;
    const int lhi = (L >> 4) * 16;
    const int lxor = (L & 7) << 4;
    const uint32_t a_row = (uint32_t)(warp_m * 32 + lrow16) * 128;
    const uint32_t b_row = (uint32_t)(warp_n * 32 + lrow16) * 128;

    for (int c = 0; c < NCH; c++) {
        if (c + 1 < NCH) asm volatile("cp.async.wait_group 1;" ::: "memory");
        else             asm volatile("cp.async.wait_group 0;" ::: "memory");
        __syncthreads();
        if (c + 2 < NCH) issue(c + 2);
        const int s = c % NST;
        const uint32_t stA = sbase + s * 24576;
        const uint32_t stB = stA + 16384;
#pragma unroll
        for (int ks = 0; ks < 4; ks++) {
            uint32_t af[2][4], bf[2][4];
            const uint32_t coff = (uint32_t)((ks * 32 + lhi) ^ lxor);
#pragma unroll
            for (int mf = 0; mf < 2; mf++)
                ldm4(af[mf], stA + a_row + mf * 2048 + coff);
#pragma unroll
            for (int nf = 0; nf < 2; nf++)
                ldm4(bf[nf], stB + b_row + nf * 2048 + coff);
#pragma unroll
            for (int mf = 0; mf < 2; mf++)
#pragma unroll
                for (int ng = 0; ng < 4; ng++)
                    mma16816(acc[mf][ng], af[mf],
                             bf[ng >> 1][ng & 1], bf[ng >> 1][(ng & 1) + 2]);
        }
    }
    __syncthreads();

    const int q = L >> 2, t2 = (L & 3) * 2;
#pragma unroll
    for (int mf = 0; mf < 2; mf++) {
        const int r0 = bm + warp_m * 32 + mf * 16 + q;
        const int r1 = r0 + 8;
#pragma unroll
        for (int ng = 0; ng < 4; ng++) {
            const int col = warp_n * 32 + ng * 8 + t2;
            *(float2*)(C + (size_t)r0 * 64 + col) = make_float2(acc[mf][ng][0], acc[mf][ng][1]);
            *(float2*)(C + (size_t)r1 * 64 + col) = make_float2(acc[mf][ng][2], acc[mf][ng][3]);
        }
    }
}

// ------------------------------------------------------------------
// LayerNorm (biased var) + ReLU over rows of g_xm, writing bf16 hi|lo
// directly into g_gate2 [row][2*CNC] (xmD2 layout).
// ------------------------------------------------------------------
__global__ void __launch_bounds__(256) ln_relu_kernel(
    const float* __restrict__ ln_g, const float* __restrict__ ln_b)
{
    const int row = blockIdx.x;
    const float* p = g_xm + (size_t)row * CNC;
    __nv_bfloat16* o = g_gate2 + (size_t)row * 2 * CNC;
    const int tid = threadIdx.x;
    float v[8];
    float s = 0.f, s2 = 0.f;
#pragma unroll
    for (int j = 0; j < 8; j++) {
        const float t = p[tid + j * 256];
        v[j] = t; s += t; s2 += t * t;
    }
#pragma unroll
    for (int o2 = 16; o2; o2 >>= 1) {
        s  += __shfl_xor_sync(0xffffffffu, s,  o2);
        s2 += __shfl_xor_sync(0xffffffffu, s2, o2);
    }
    __shared__ float ss[8], ss2[8], sh[2];
    if ((tid & 31) == 0) { ss[tid >> 5] = s; ss2[tid >> 5] = s2; }
    __syncthreads();
    if (tid == 0) {
        float t = 0.f, t2 = 0.f;
#pragma unroll
        for (int i = 0; i < 8; i++) { t += ss[i]; t2 += ss2[i]; }
        const float mu  = t * (1.0f / CNC);
        const float var = t2 * (1.0f / CNC) - mu * mu;
        sh[0] = mu; sh[1] = rsqrtf(var + CLN_EPS);
    }
    __syncthreads();
    const float mu = sh[0], rs = sh[1];
#pragma unroll
    for (int j = 0; j < 8; j++) {
        const int c = tid + j * 256;
        const float y = (v[j] - mu) * rs * ln_g[c] + ln_b[c];
        const float r = fmaxf(y, 0.f);
        const __nv_bfloat16 h = __float2bfloat16(r);
        o[c]       = h;
        o[CNC + c] = __float2bfloat16(r - __bfloat162float(h));
    }
}

// ------------------------------------------------------------------
// Broadcast bases0 (1, S, R) -> g_bases (B, S, R) AND g_basT2 [b][r][2D]
// ------------------------------------------------------------------
__global__ void __launch_bounds__(256) bcast_bases_kernel(const float* __restrict__ b0)
{
    const int i = blockIdx.x * 256 + threadIdx.x;     // over CB*CS*CR
    const int e = i & (CS * CR - 1);
    const int b = i >> 16;                            // CS*CR = 65536
    const float v = b0[e];
    g_bases[i] = v;
    const int s = e >> 6, r = e & 63;
    const __nv_bfloat16 h = __float2bfloat16(v);
    __nv_bfloat16* row = g_basT2 + (size_t)b * (CR * 2 * CS) + (size_t)r * 2 * CS;
    row[s]      = h;
    row[CS + s] = __float2bfloat16(v - __bfloat162float(h));
}

// ------------------------------------------------------------------
// TN skinny GEMM (SIMT) — used ONCE for the initial btb Gram.
// ------------------------------------------------------------------
__global__ void __launch_bounds__(256) gemm_tn64_kernel(
    const float* __restrict__ A, const float* __restrict__ Bv, float* __restrict__ C,
    int M, int lda, int Ktot, int ksplit,
    long strideA, long strideB, long strideC, long partStride)
{
    const int b = blockIdx.z;
    const int Kloc = Ktot / ksplit;
    const long koff = (long)blockIdx.y * Kloc;
    const float* Ab = A + (long)b * strideA + koff * lda;
    const float* Bb = Bv + (long)b * strideB + koff * 64;
    float* Cb = C + (long)b * strideC + (long)blockIdx.y * partStride;
    const int bm = blockIdx.x * 128;

    __shared__ float Asm[16][128];
    __shared__ float Bsm[16][64];
    const int tid = threadIdx.x;
    const int tm = tid & 31, tr = tid >> 5;
    float acc[4][8];
#pragma unroll
    for (int i = 0; i < 4; i++)
#pragma unroll
        for (int j = 0; j < 8; j++) acc[i][j] = 0.f;

    for (int k0 = 0; k0 < Kloc; k0 += 16) {
#pragma unroll
        for (int i = 0; i < 8; i++) {
            const int idx = tid + i * 256;
            const int kk = idx >> 7, mm = idx & 127;
            const int gm = bm + mm;
            Asm[kk][mm] = (gm < M) ? Ab[(long)(k0 + kk) * lda + gm] : 0.f;
        }
#pragma unroll
        for (int i = 0; i < 4; i++) {
            const int idx = tid + i * 256;
            const int kk = idx >> 6, rr = idx & 63;
            Bsm[kk][rr] = Bb[(long)(k0 + kk) * 64 + rr];
        }
        __syncthreads();
#pragma unroll
        for (int kk = 0; kk < 16; kk++) {
            float ra[4], rb[8];
            *(float4*)ra      = *(const float4*)&Asm[kk][tm * 4];
            *(float4*)&rb[0]  = *(const float4*)&Bsm[kk][tr * 8];
            *(float4*)&rb[4]  = *(const float4*)&Bsm[kk][tr * 8 + 4];
#pragma unroll
            for (int i = 0; i < 4; i++)
#pragma unroll
                for (int j = 0; j < 8; j++)
                    acc[i][j] = fmaf(ra[i], rb[j], acc[i][j]);
        }
        __syncthreads();
    }
#pragma unroll
    for (int i = 0; i < 4; i++) {
        const int m = bm + tm * 4 + i;
        if (m < M) {
#pragma unroll
            for (int j = 0; j < 8; j++)
                Cb[(long)m * 64 + tr * 8 + j] = acc[i][j];
        }
    }
}

// ------------------------------------------------------------------
// Fused NMF multiplicative update:
//   Cout[m,r] *= (sum_q Num_part[q][m,r]) / ((Cout @ sum_p Gin_part[p]) + eps)
// then ALSO:
//   - writes T2out [r][2*Ndim] hi|lo transposed-packed slice (cols bm..bm+127)
//   - writes Gram partial  Gout[blockIdx.x][r][s] = sum_{m in tile} v[m,r]*v[m,s]
// grid (Mtiles, 1, CB), 256 threads. K = 64 fixed (rank).
// ------------------------------------------------------------------
__global__ void __launch_bounds__(256) nmf_update_kernel(
    const float* __restrict__ Gin, const float* __restrict__ Num,
    float* __restrict__ Cout, __nv_bfloat16* __restrict__ T2out,
    float* __restrict__ Gout,
    int npartIn, int numPartN, int Ndim,
    long strideC, long strideGin, long strideNum, long strideT2, long strideGout,
    long numPartStride)
{
    const int b = blockIdx.z;
    float* Cb = Cout + (long)b * strideC;
    const float* Gb = Gin + (long)b * strideGin;
    const float* Nb = Num + (long)b * strideNum;
    __nv_bfloat16* Tb = T2out + (long)b * strideT2;
    float* Ob = Gout + (long)b * strideGout + (long)blockIdx.x * (CR * CR);
    const int bm = blockIdx.x * 128;

    __shared__ float Asm[16][132];
    __shared__ float Bsm[16][64];
    __shared__ float T[64][132];
    const int tid = threadIdx.x;
    const int tm = tid & 31, tr = tid >> 5;
    float acc[4][8];
#pragma unroll
    for (int i = 0; i < 4; i++)
#pragma unroll
        for (int j = 0; j < 8; j++) acc[i][j] = 0.f;

    for (int k0 = 0; k0 < 64; k0 += 16) {
#pragma unroll
        for (int i = 0; i < 8; i++) {
            const int idx = tid + i * 256;
            const int mm = idx >> 4, kk = idx & 15;
            Asm[kk][mm] = Cb[(long)(bm + mm) * 64 + k0 + kk];
        }
#pragma unroll
        for (int i = 0; i < 4; i++) {
            const int idx = tid + i * 256;
            const int kk = idx >> 6, rr = idx & 63;
            float v = 0.f;
            for (int p = 0; p < npartIn; p++)
                v += Gb[(long)p * (CR * CR) + (long)(k0 + kk) * 64 + rr];
            Bsm[kk][rr] = v;
        }
        __syncthreads();
#pragma unroll
        for (int kk = 0; kk < 16; kk++) {
            float ra[4], rb[8];
            *(float4*)ra     = *(const float4*)&Asm[kk][tm * 4];
            *(float4*)&rb[0] = *(const float4*)&Bsm[kk][tr * 8];
            *(float4*)&rb[4] = *(const float4*)&Bsm[kk][tr * 8 + 4];
#pragma unroll
            for (int i = 0; i < 4; i++)
#pragma unroll
                for (int j = 0; j < 8; j++)
                    acc[i][j] = fmaf(ra[i], rb[j], acc[i][j]);
        }
        __syncthreads();
    }

    // multiplicative update + write Cout + stage into transpose buffer T[r][mlocal]
#pragma unroll
    for (int i = 0; i < 4; i++) {
        const int mloc = tm * 4 + i;
        const int m = bm + mloc;
#pragma unroll
        for (int j = 0; j < 8; j++) {
            const int r = tr * 8 + j;
            const long idx = (long)m * 64 + r;
            float nv = 0.f;
            for (int q = 0; q < numPartN; q++)
                nv += Nb[q * numPartStride + idx];
            const float v = Cb[idx] * nv / (acc[i][j] + NMF_EPS);
            Cb[idx] = v;
            T[r][mloc] = v;
        }
    }
    __syncthreads();

    // transposed hi|lo pack write: T2out[r][bm + mloc] (+Ndim for lo)
#pragma unroll
    for (int k = 0; k < 32; k++) {
        const int e = tid + k * 256;          // 8192 values
        const int r = e >> 7, mloc = e & 127;
        const float v = T[r][mloc];
        const __nv_bfloat16 h = __float2bfloat16(v);
        __nv_bfloat16* row = Tb + (size_t)r * 2 * Ndim + bm + mloc;
        row[0]    = h;
        row[Ndim] = __float2bfloat16(v - __bfloat162float(h));
    }

    // Gram partial from this tile: Ob[r][s] = sum_m T[r][m]*T[s][m]
    {
        const int tr2 = tid >> 4, tc2 = tid & 15;   // 4x4 output block
        float g[4][4];
#pragma unroll
        for (int i = 0; i < 4; i++)
#pragma unroll
            for (int j = 0; j < 4; j++) g[i][j] = 0.f;
        for (int n = 0; n < 128; n += 4) {
            float4 ra[4], rb[4];
#pragma unroll
            for (int i = 0; i < 4; i++) ra[i] = *(const float4*)&T[tr2 * 4 + i][n];
#pragma unroll
            for (int j = 0; j < 4; j++) rb[j] = *(const float4*)&T[tc2 * 4 + j][n];
#pragma unroll
            for (int i = 0; i < 4; i++)
#pragma unroll
                for (int j = 0; j < 4; j++)
                    g[i][j] += ra[i].x * rb[j].x + ra[i].y * rb[j].y
                             + ra[i].z * rb[j].z + ra[i].w * rb[j].w;
        }
#pragma unroll
        for (int i = 0; i < 4; i++)
#pragma unroll
            for (int j = 0; j < 4; j++)
                Ob[(tr2 * 4 + i) * 64 + tc2 * 4 + j] = g[i][j];
    }
}

// ------------------------------------------------------------------
// Row softmax over R=64 on sum of NSPL partials of g_numn -> g_coef.
// ------------------------------------------------------------------
__global__ void __launch_bounds__(256) softmax64_kernel()
{
    const int row = blockIdx.x * 8 + (threadIdx.x >> 5);
    const int l = threadIdx.x & 31;
    const float* src = g_numn + (size_t)row * 64;
    float a = src[l] + src[PARTN + l];
    float c = src[l + 32] + src[PARTN + l + 32];
    float mx = fmaxf(a, c);
#pragma unroll
    for (int o = 16; o; o >>= 1) mx = fmaxf(mx, __shfl_xor_sync(0xffffffffu, mx, o));
    a = expf(a - mx); c = expf(c - mx);
    float s = a + c;
#pragma unroll
    for (int o = 16; o; o >>= 1) s += __shfl_xor_sync(0xffffffffu, s, o);
    const float inv = 1.f / s;
    float* dst = g_coef + (size_t)row * 64;
    dst[l] = a * inv; dst[l + 32] = c * inv;
}

// ------------------------------------------------------------------
// Reconstruct + gate, writing bf16 hi|lo directly into g_gate2
// ------------------------------------------------------------------
__global__ void __launch_bounds__(256) recon_gate_kernel()
{
    const int b  = blockIdx.z;
    const int bd = blockIdx.y * 64;
    const int bn = blockIdx.x * 64;
    const float* bas = g_bases + (size_t)b * CS * CR;
    const float* cof = g_coef  + (size_t)b * CNC * CR;
    __shared__ float Bas[CR][68];
    __shared__ float Cof[CR][68];
    const int tid = threadIdx.x;
#pragma unroll
    for (int i = 0; i < 16; i++) {
        const int idx = tid + i * 256;
        const int dd = idx >> 6, rr = idx & 63;
        Bas[rr][dd] = bas[(size_t)(bd + dd) * CR + rr];
    }
#pragma unroll
    for (int i = 0; i < 16; i++) {
        const int idx = tid + i * 256;
        const int nn = idx >> 6, rr = idx & 63;
        Cof[rr][nn] = cof[(size_t)(bn + nn) * CR + rr];
    }
    __syncthreads();
    const int td = tid >> 4, tn = tid & 15;
    float acc[4][4];
#pragma unroll
    for (int i = 0; i < 4; i++)
#pragma unroll
        for (int j = 0; j < 4; j++) acc[i][j] = 0.f;
#pragma unroll
    for (int r = 0; r < CR; r++) {
        float ra[4], rb[4];
        *(float4*)ra = *(const float4*)&Bas[r][td * 4];
        *(float4*)rb = *(const float4*)&Cof[r][tn * 4];
#pragma unroll
        for (int i = 0; i < 4; i++)
#pragma unroll
            for (int j = 0; j < 4; j++)
                acc[i][j] = fmaf(ra[i], rb[j], acc[i][j]);
    }
#pragma unroll
    for (int i = 0; i < 4; i++) {
        const int d = bd + td * 4 + i;
        const size_t zoff = ((size_t)b * CS + d) * CNC;
        __nv_bfloat16* orow = g_gate2 + ((size_t)b * CS + d) * 2 * CNC;
#pragma unroll
        for (int j = 0; j < 4; j++) {
            const int n = bn + tn * 4 + j;
            const float v = g_z1[zoff + n] * acc[i][j];
            const __nv_bfloat16 h = __float2bfloat16(v);
            orow[n]       = h;
            orow[CNC + n] = __float2bfloat16(v - __bfloat162float(h));
        }
    }
}

// ------------------------------------------------------------------
// Launch sequence
// ------------------------------------------------------------------
extern "C" void kernel_launch(void* const* d_in, const int* in_sizes, int n_in,
                              void* d_out, int out_size)
{
    const float* x    = (const float*)d_in[0];
    const float* U_w  = (const float*)d_in[1];
    const float* U_b  = (const float*)d_in[2];
    const float* ln_g = (const float*)d_in[3];
    const float* ln_b = (const float*)d_in[4];
    const float* bas0 = (const float*)d_in[5];
    const float* V_w  = (const float*)d_in[6];
    const float* V_b  = (const float*)d_in[7];
    float* out = (float*)d_out;

    float *z1, *xm, *coef, *bases, *numn, *numd, *btb, *ctc;
    __nv_bfloat16 *xh2, *uw2, *gate2, *vw2, *xmT2, *basT2, *cofT2;
    cudaGetSymbolAddress((void**)&z1,    g_z1);
    cudaGetSymbolAddress((void**)&xm,    g_xm);
    cudaGetSymbolAddress((void**)&coef,  g_coef);
    cudaGetSymbolAddress((void**)&bases, g_bases);
    cudaGetSymbolAddress((void**)&numn,  g_numn);
    cudaGetSymbolAddress((void**)&numd,  g_numd);
    cudaGetSymbolAddress((void**)&btb,   g_btb);
    cudaGetSymbolAddress((void**)&ctc,   g_ctc);
    cudaGetSymbolAddress((void**)&xh2,   g_xh2);
    cudaGetSymbolAddress((void**)&uw2,   g_uw2);
    cudaGetSymbolAddress((void**)&gate2, g_gate2);
    cudaGetSymbolAddress((void**)&vw2,   g_vw2);
    cudaGetSymbolAddress((void**)&xmT2,  g_xmT2);
    cudaGetSymbolAddress((void**)&basT2, g_basT2);
    cudaGetSymbolAddress((void**)&cofT2, g_cofT2);

    cudaFuncSetAttribute(gemm_tc_kernel<0>, cudaFuncAttributeMaxDynamicSharedMemorySize, TCSMEM);
    cudaFuncSetAttribute(gemm_tc_kernel<1>, cudaFuncAttributeMaxDynamicSharedMemorySize, TCSMEM);
    cudaFuncSetAttribute(gemm_tc64_kernel, cudaFuncAttributeMaxDynamicSharedMemorySize, TC64SMEM);

    const long S_BAS = (long)CS * CR;
    const long S_CO  = (long)CNC * CR;
    const long SA_T = (long)CNC * 2 * CS;   // xmT2 per-batch
    const long SB_T = (long)CR * 2 * CS;    // basT2 per-batch
    const long SA_D = (long)CS * 2 * CNC;   // gate2 (xmD2) per-batch
    const long SB_D = (long)CR * 2 * CNC;   // cofT2 per-batch
    const long S_BTB = (long)BPARTS * CR * CR;
    const long S_CTC = (long)CPARTS * CR * CR;

    auto tc_numn = [&]() {
        gemm_tc64_kernel<<<dim3(CNC / 128, NSPL, CB), 256, TC64SMEM>>>(
            xmT2, basT2, numn, CS, CS / NSPL, SA_T, SB_T, S_CO, PARTN);
    };
    // coef update: reads btb(8 parts)+numn(2 parts); writes coef, cofT2, ctc(16 parts)
    auto upd_coef = [&]() {
        nmf_update_kernel<<<dim3(CNC / 128, 1, CB), 256>>>(
            btb, numn, coef, cofT2, ctc,
            BPARTS, NSPL, CNC,
            S_CO, S_BTB, S_CO, SB_D, S_CTC, PARTN);
    };
    // bases update: reads ctc(16 parts)+numd(4 parts); writes bases, basT2, btb(8 parts)
    auto upd_bases = [&]() {
        nmf_update_kernel<<<dim3(CS / 128, 1, CB), 256>>>(
            ctc, numd, bases, basT2, btb,
            CPARTS, DSPL, CS,
            S_BAS, S_CTC, S_BAS, SB_T, S_BTB, PARTD);
    };

    // 0) split-pack x, U_w, V_w to bf16 hi|lo
    pack_kernel<<<(CBS * CF / 4) / 256, 256>>>(x, xh2, 10, CBS * CF / 4);
    pack_kernel<<<(CFFN * CF / 4) / 256, 256>>>(U_w, uw2, 10, CFFN * CF / 4);
    pack_kernel<<<(CF * CNC / 4) / 256, 256>>>(V_w, vw2, 11, CF * CNC / 4);

    // 1) h = gelu(x @ U_w^T + U_b), split into z1 / xm (z2 pre-LN)
    gemm_tc_kernel<0><<<dim3(CFFN / 128, CBS / 128), 256, TCSMEM>>>(
        xh2, uw2, U_b, z1, xm, CF, CFFN);

    // 2) LayerNorm + ReLU -> packed xmD2 in gate2
    ln_relu_kernel<<<CBS, 256>>>(ln_g, ln_b);

    // 3) broadcast bases (+ initial basT2); build xm^T packed layout
    bcast_bases_kernel<<<(CB * CS * CR) / 256, 256>>>(bas0);
    transpack_bf_kernel<<<dim3(CNC / 32, CS / 32, CB), dim3(32, 8)>>>(
        gate2, xmT2, CS, CNC, SA_D, SA_T);

    // 4) coef = softmax(xm^T @ bases); initial btb Gram (SIMT, once)
    tc_numn();
    softmax64_kernel<<<(CB * CNC) / 8, 256>>>();
    gemm_tn64_kernel<<<dim3(1, GSPLIT, CB), 256>>>(
        bases, bases, btb, CR, CR, CS, GSPLIT, S_BAS, S_BAS, S_BTB, (long)CR * CR);

    // 5) 6 NMF steps (numn from init reused at it=0: bases unchanged)
    for (int it = 0; it < NSTEPS; it++) {
        if (it > 0) tc_numn();
        upd_coef();       // coef, cofT2, ctc partials
        gemm_tc64_kernel<<<dim3(CS / 128, DSPL, CB), 256, TC64SMEM>>>(
            gate2, cofT2, numd, CNC, CNC / DSPL, SA_D, SB_D, S_BAS, PARTD);
        upd_bases();      // bases, basT2, btb partials (for next step)
    }

    // 6) final coef update (compute_coef) — uses btb from last bases update
    tc_numn();
    upd_coef();

    // 7) gated reconstruction -> packed gate2
    recon_gate_kernel<<<dim3(CNC / 64, CS / 64, CB), 256>>>();

    // 8) out = gated @ V_w^T + V_b
    gemm_tc_kernel<1><<<dim3(CF / 128, CBS / 128), 256, TCSMEM>>>(
        gate2, vw2, V_b, out, nullptr, CNC, CF);
}